// round 3
// baseline (speedup 1.0000x reference)
#include <cuda_runtime.h>
#include <cuda_bf16.h>
#include <cstdint>
#include <cstddef>

#define TSTEPS 1024
#define GDIM   1024
#define HSEQ   ((size_t)TSTEPS * 256 * 256)

__device__ float g_xpb[(size_t)TSTEPS * 256 * GDIM];   // x@W_ih + bias
__device__ float g_h[256 * 256];                        // h state
__device__ float g_gates[256 * GDIM];                   // per-step gates
__device__ unsigned long long g_bar;                    // grid barrier counter

__device__ __forceinline__ float f2tf(float x) {
    uint32_t r; asm("cvt.rna.tf32.f32 %0, %1;" : "=r"(r) : "f"(x));
    return __uint_as_float(r);
}
__device__ __forceinline__ uint32_t sptr(const void* p) {
    return (uint32_t)__cvta_generic_to_shared(p);
}
__device__ __forceinline__ void ldsm4(uint32_t a[4], uint32_t addr) {
    asm volatile("ldmatrix.sync.aligned.m8n8.x4.shared.b16 {%0,%1,%2,%3}, [%4];"
        : "=r"(a[0]), "=r"(a[1]), "=r"(a[2]), "=r"(a[3]) : "r"(addr));
}
__device__ __forceinline__ void mma8(float c[4], const uint32_t a[4], uint32_t b0, uint32_t b1) {
    asm volatile("mma.sync.aligned.m16n8k8.row.col.f32.tf32.tf32.f32 "
        "{%0,%1,%2,%3}, {%4,%5,%6,%7}, {%8,%9}, {%0,%1,%2,%3};"
        : "+f"(c[0]), "+f"(c[1]), "+f"(c[2]), "+f"(c[3])
        : "r"(a[0]), "r"(a[1]), "r"(a[2]), "r"(a[3]), "r"(b0), "r"(b1));
}
__device__ __forceinline__ float sigf(float x) { return 1.f / (1.f + __expf(-x)); }

__device__ __forceinline__ void gsync(unsigned long long target) {
    __syncthreads();
    if (threadIdx.x == 0) {
        __threadfence();
        atomicAdd(&g_bar, 1ULL);
        while (*(volatile unsigned long long*)&g_bar < target * 128ULL) { }
    }
    __syncthreads();
}

// ============================================================================
// Projection: g_xpb = X(262144x256) @ W_ih(256x1024) + bias, tf32 mma
// CTA tile 32Mx128N, 8 warps (2m x 4n), warp tile 16x32, K chunks of 64.
// ============================================================================
#define ASTR 68    // 64 k + pad (4-word row offset: conflict-free ldmatrix)
#define BSTR 136   // 128 n + pad (8-word row offset: conflict-free b-frag LDS)

__global__ void __launch_bounds__(256) proj_kernel(const float* __restrict__ X,
                                                   const float* __restrict__ W,
                                                   const float* __restrict__ bias) {
    __shared__ float As[32 * ASTR];
    __shared__ float Bs[64 * BSTR];
    const int tid = threadIdx.x;
    const int nb = blockIdx.x * 128, mb = blockIdx.y * 32;
    const int w = tid >> 5, lane = tid & 31;
    const int g = lane >> 2, t4 = lane & 3;
    const int mw = w & 1, nw = w >> 1;

    float acc[4][4] = {};
    const uint32_t abase = sptr(As + (mw * 16 + (lane & 15)) * ASTR + (lane >> 4) * 4);

    for (int kc = 0; kc < 4; kc++) {
        if (kc) __syncthreads();
        // stage A 32x64 (tf32-rounded)
        #pragma unroll
        for (int i = 0; i < 2; i++) {
            int idx = tid + 256 * i, r = idx >> 4, c4 = idx & 15;
            float4 v = *(const float4*)(X + (size_t)(mb + r) * 256 + kc * 64 + c4 * 4);
            v.x = f2tf(v.x); v.y = f2tf(v.y); v.z = f2tf(v.z); v.w = f2tf(v.w);
            *(float4*)(As + r * ASTR + c4 * 4) = v;
        }
        // stage B 64x128 (tf32-rounded)
        #pragma unroll
        for (int i = 0; i < 8; i++) {
            int idx = tid + 256 * i, r = idx >> 5, c4 = idx & 31;
            float4 v = *(const float4*)(W + (size_t)(kc * 64 + r) * GDIM + nb + c4 * 4);
            v.x = f2tf(v.x); v.y = f2tf(v.y); v.z = f2tf(v.z); v.w = f2tf(v.w);
            *(float4*)(Bs + r * BSTR + c4 * 4) = v;
        }
        __syncthreads();
        #pragma unroll
        for (int kt = 0; kt < 8; kt++) {
            uint32_t a[4];
            ldsm4(a, abase + kt * 32);
            #pragma unroll
            for (int nt = 0; nt < 4; nt++) {
                int col = nw * 32 + nt * 8 + g;
                uint32_t b0 = __float_as_uint(Bs[(kt * 8 + t4) * BSTR + col]);
                uint32_t b1 = __float_as_uint(Bs[(kt * 8 + t4 + 4) * BSTR + col]);
                mma8(acc[nt], a, b0, b1);
            }
        }
    }
    size_t rbase = (size_t)(mb + mw * 16 + g) * GDIM;
    #pragma unroll
    for (int nt = 0; nt < 4; nt++) {
        int col = nb + nw * 32 + nt * 8 + 2 * t4;
        float b0 = __ldg(bias + col), b1 = __ldg(bias + col + 1);
        *(float2*)(g_xpb + rbase + col) = make_float2(acc[nt][0] + b0, acc[nt][1] + b1);
        *(float2*)(g_xpb + rbase + 8 * GDIM + col) = make_float2(acc[nt][2] + b0, acc[nt][3] + b1);
    }
}

__global__ void reset_kernel() { g_bar = 0ULL; }

// ============================================================================
// Recurrence: persistent, 128 CTAs x 256 thr. CTA(ci,cj): rows 32ci..+32,
// gate cols 64cj..+64. W_hh slice pre-converted into mma B-fragments in regs.
// ============================================================================
#define HSTR 260   // 256 k + pad (4-word row offset)

__global__ void __launch_bounds__(256) lstm_kernel(const float* __restrict__ Whh,
                                                   float* __restrict__ out,
                                                   int tail) {
    __shared__ float As[32 * HSTR];
    const int tid = threadIdx.x;
    const int ci = blockIdx.x >> 4, cj = blockIdx.x & 15;
    const int w = tid >> 5, lane = tid & 31;
    const int g = lane >> 2, t4 = lane & 3;
    const int mw = w & 1, nw = w >> 1;   // warp tile 16M x 16N (2m x 4n)

    // preload W_hh B-fragments (persist across all steps)
    uint32_t bf[32][2][2];
    #pragma unroll
    for (int kt = 0; kt < 32; kt++)
        #pragma unroll
        for (int nt = 0; nt < 2; nt++) {
            int col = cj * 64 + nw * 16 + nt * 8 + g;
            bf[kt][nt][0] = __float_as_uint(f2tf(Whh[(size_t)(kt * 8 + t4) * GDIM + col]));
            bf[kt][nt][1] = __float_as_uint(f2tf(Whh[(size_t)(kt * 8 + t4 + 4) * GDIM + col]));
        }

    // pointwise ownership: 2 elements/thread of the 32x16 (row x hcol) block
    const int pr0 = ci * 32 + (tid >> 4),        ph0 = cj * 16 + (tid & 15);
    const int pr1 = ci * 32 + ((tid + 256) >> 4), ph1 = cj * 16 + (tid & 15);
    float c0 = 0.f, c1 = 0.f;

    const uint32_t abase = sptr(As + (mw * 16 + (lane & 15)) * HSTR + (lane >> 4) * 4);
    unsigned long long k = 0;

    for (int t = 0; t < TSTEPS; t++) {
        float acc[2][4] = {};
        if (t) {
            // stage h rows (tf32-rounded), read via L2
            #pragma unroll
            for (int i = 0; i < 8; i++) {
                int idx = tid + 256 * i, r = idx >> 6, c4 = idx & 63;
                float4 v = __ldcg((const float4*)(g_h + (size_t)(ci * 32 + r) * 256 + c4 * 4));
                v.x = f2tf(v.x); v.y = f2tf(v.y); v.z = f2tf(v.z); v.w = f2tf(v.w);
                *(float4*)(As + r * HSTR + c4 * 4) = v;
            }
            __syncthreads();
            #pragma unroll
            for (int kt = 0; kt < 32; kt++) {
                uint32_t a[4];
                ldsm4(a, abase + kt * 32);
                mma8(acc[0], a, bf[kt][0][0], bf[kt][0][1]);
                mma8(acc[1], a, bf[kt][1][0], bf[kt][1][1]);
            }
        }
        // gates = acc + xp_t  -> global
        size_t xoff = (size_t)t * (256 * GDIM);
        #pragma unroll
        for (int half = 0; half < 2; half++) {
            int row = ci * 32 + mw * 16 + g + half * 8;
            #pragma unroll
            for (int nt = 0; nt < 2; nt++) {
                int col = cj * 64 + nw * 16 + nt * 8 + 2 * t4;
                float2 v = __ldcg((const float2*)(g_xpb + xoff + (size_t)row * GDIM + col));
                *(float2*)(g_gates + (size_t)row * GDIM + col) =
                    make_float2(acc[nt][half * 2] + v.x, acc[nt][half * 2 + 1] + v.y);
            }
        }
        gsync(++k);
        // pointwise LSTM update (c in registers)
        {
            float i0 = sigf(__ldcg(g_gates + pr0 * GDIM + ph0));
            float f0 = sigf(__ldcg(g_gates + pr0 * GDIM + 256 + ph0));
            float gg0 = tanhf(__ldcg(g_gates + pr0 * GDIM + 512 + ph0));
            float o0 = sigf(__ldcg(g_gates + pr0 * GDIM + 768 + ph0));
            c0 = f0 * c0 + i0 * gg0;
            float h0 = o0 * tanhf(c0);
            float i1 = sigf(__ldcg(g_gates + pr1 * GDIM + ph1));
            float f1 = sigf(__ldcg(g_gates + pr1 * GDIM + 256 + ph1));
            float gg1 = tanhf(__ldcg(g_gates + pr1 * GDIM + 512 + ph1));
            float o1 = sigf(__ldcg(g_gates + pr1 * GDIM + 768 + ph1));
            c1 = f1 * c1 + i1 * gg1;
            float h1 = o1 * tanhf(c1);
            g_h[pr0 * 256 + ph0] = h0;
            g_h[pr1 * 256 + ph1] = h1;
            out[(size_t)t * 65536 + pr0 * 256 + ph0] = h0;
            out[(size_t)t * 65536 + pr1 * 256 + ph1] = h1;
            if (tail && t == TSTEPS - 1) {
                out[HSEQ + pr0 * 256 + ph0] = h0;
                out[HSEQ + pr1 * 256 + ph1] = h1;
                out[HSEQ + 65536 + pr0 * 256 + ph0] = c0;
                out[HSEQ + 65536 + pr1 * 256 + ph1] = c1;
            }
        }
        gsync(++k);
    }
}

extern "C" void kernel_launch(void* const* d_in, const int* in_sizes, int n_in,
                              void* d_out, int out_size) {
    const float* x    = (const float*)d_in[0];
    const float* wih  = (const float*)d_in[1];
    const float* whh  = (const float*)d_in[2];
    const float* bias = (const float*)d_in[3];
    float* out = (float*)d_out;
    (void)in_sizes; (void)n_in;
    proj_kernel<<<dim3(8, 8192), 256>>>(x, wih, bias);
    reset_kernel<<<1, 1>>>();
    int tail = ((size_t)out_size >= HSEQ + 2 * 65536) ? 1 : 0;
    lstm_kernel<<<128, 256>>>(whh, out, tail);
}

// round 4
// speedup vs baseline: 1.2459x; 1.2459x over previous
#include <cuda_runtime.h>
#include <cuda_bf16.h>
#include <cstdint>
#include <cstddef>

typedef unsigned long long ull;

#define TSTEPS 1024
#define GDIM   1024
#define HSEQ   ((size_t)TSTEPS * 256 * 256)

__device__ float g_xpb[(size_t)TSTEPS * 256 * GDIM];   // x@W_ih + bias

__device__ __forceinline__ float f2tf(float x) {
    uint32_t r; asm("cvt.rna.tf32.f32 %0, %1;" : "=r"(r) : "f"(x));
    return __uint_as_float(r);
}
__device__ __forceinline__ uint32_t sptr(const void* p) {
    return (uint32_t)__cvta_generic_to_shared(p);
}
__device__ __forceinline__ void ldsm4(uint32_t a[4], uint32_t addr) {
    asm volatile("ldmatrix.sync.aligned.m8n8.x4.shared.b16 {%0,%1,%2,%3}, [%4];"
        : "=r"(a[0]), "=r"(a[1]), "=r"(a[2]), "=r"(a[3]) : "r"(addr));
}
__device__ __forceinline__ void mma8(float c[4], const uint32_t a[4], uint32_t b0, uint32_t b1) {
    asm volatile("mma.sync.aligned.m16n8k8.row.col.f32.tf32.tf32.f32 "
        "{%0,%1,%2,%3}, {%4,%5,%6,%7}, {%8,%9}, {%0,%1,%2,%3};"
        : "+f"(c[0]), "+f"(c[1]), "+f"(c[2]), "+f"(c[3])
        : "r"(a[0]), "r"(a[1]), "r"(a[2]), "r"(a[3]), "r"(b0), "r"(b1));
}
__device__ __forceinline__ float sigf(float x) { return 1.f / (1.f + __expf(-x)); }
__device__ __forceinline__ ull pack2(float x, float y) {
    ull r; asm("mov.b64 %0, {%1, %2};" : "=l"(r) : "f"(x), "f"(y)); return r;
}
__device__ __forceinline__ uint32_t mapa_rank(uint32_t addr, uint32_t rank) {
    uint32_t r;
    asm("mapa.shared::cluster.u32 %0, %1, %2;" : "=r"(r) : "r"(addr), "r"(rank));
    return r;
}
__device__ __forceinline__ void st_cluster64(uint32_t addr, ull v) {
    asm volatile("st.shared::cluster.u64 [%0], %1;" :: "r"(addr), "l"(v) : "memory");
}

// ============================================================================
// Projection: g_xpb = X(262144x256) @ W_ih(256x1024) + bias, tf32 mma
// (unchanged from R3 — known correct; optimize next round)
// ============================================================================
#define ASTR 68
#define BSTR 136

__global__ void __launch_bounds__(256) proj_kernel(const float* __restrict__ X,
                                                   const float* __restrict__ W,
                                                   const float* __restrict__ bias) {
    __shared__ float As[32 * ASTR];
    __shared__ float Bs[64 * BSTR];
    const int tid = threadIdx.x;
    const int nb = blockIdx.x * 128, mb = blockIdx.y * 32;
    const int w = tid >> 5, lane = tid & 31;
    const int g = lane >> 2, t4 = lane & 3;
    const int mw = w & 1, nw = w >> 1;

    float acc[4][4] = {};
    const uint32_t abase = sptr(As + (mw * 16 + (lane & 15)) * ASTR + (lane >> 4) * 4);

    for (int kc = 0; kc < 4; kc++) {
        if (kc) __syncthreads();
        #pragma unroll
        for (int i = 0; i < 2; i++) {
            int idx = tid + 256 * i, r = idx >> 4, c4 = idx & 15;
            float4 v = *(const float4*)(X + (size_t)(mb + r) * 256 + kc * 64 + c4 * 4);
            v.x = f2tf(v.x); v.y = f2tf(v.y); v.z = f2tf(v.z); v.w = f2tf(v.w);
            *(float4*)(As + r * ASTR + c4 * 4) = v;
        }
        #pragma unroll
        for (int i = 0; i < 8; i++) {
            int idx = tid + 256 * i, r = idx >> 5, c4 = idx & 31;
            float4 v = *(const float4*)(W + (size_t)(kc * 64 + r) * GDIM + nb + c4 * 4);
            v.x = f2tf(v.x); v.y = f2tf(v.y); v.z = f2tf(v.z); v.w = f2tf(v.w);
            *(float4*)(Bs + r * BSTR + c4 * 4) = v;
        }
        __syncthreads();
        #pragma unroll
        for (int kt = 0; kt < 8; kt++) {
            uint32_t a[4];
            ldsm4(a, abase + kt * 32);
            #pragma unroll
            for (int nt = 0; nt < 4; nt++) {
                int col = nw * 32 + nt * 8 + g;
                uint32_t b0 = __float_as_uint(Bs[(kt * 8 + t4) * BSTR + col]);
                uint32_t b1 = __float_as_uint(Bs[(kt * 8 + t4 + 4) * BSTR + col]);
                mma8(acc[nt], a, b0, b1);
            }
        }
    }
    size_t rbase = (size_t)(mb + mw * 16 + g) * GDIM;
    #pragma unroll
    for (int nt = 0; nt < 4; nt++) {
        int col = nb + nw * 32 + nt * 8 + 2 * t4;
        float b0 = __ldg(bias + col), b1 = __ldg(bias + col + 1);
        *(float2*)(g_xpb + rbase + col) = make_float2(acc[nt][0] + b0, acc[nt][1] + b1);
        *(float2*)(g_xpb + rbase + 8 * GDIM + col) = make_float2(acc[nt][2] + b0, acc[nt][3] + b1);
    }
}

// ============================================================================
// Recurrence: 16 clusters x 8 CTAs. Cluster owns 16 rows; CTA r owns h-cols
// [32r,32r+32) and the 4 matching 32-wide gate blocks. W_hh B-frags in regs.
// h exchanged via DSMEM push into double-buffered As; ONE cluster barrier/step.
// ============================================================================
#define HSTR 260   // 256 k + pad
#define GSTR 132   // 128 gate cols + pad

__global__ void __launch_bounds__(256, 1) __cluster_dims__(8, 1, 1)
lstm_kernel(const float* __restrict__ Whh, float* __restrict__ out, int tail) {
    __shared__ float As[2][16 * HSTR];   // tf32 h tiles (read buf = t&1)
    __shared__ float gs[16 * GSTR];      // mma partial gates

    const int tid = threadIdx.x;
    const int w = tid >> 5, lane = tid & 31;
    const int g = lane >> 2, t4 = lane & 3;
    const int cid = blockIdx.x >> 3;
    uint32_t r; asm("mov.u32 %0, %%cluster_ctarank;" : "=r"(r));

    // W_hh slice as persistent mma B-fragments (128 regs)
    uint32_t bf[32][2][2];
    #pragma unroll
    for (int kt = 0; kt < 32; kt++)
        #pragma unroll
        for (int nt = 0; nt < 2; nt++) {
            int l = w * 16 + nt * 8 + g;                       // local gate col 0..127
            int gcol = (l >> 5) * 256 + (int)r * 32 + (l & 31); // global gate col
            bf[kt][nt][0] = __float_as_uint(f2tf(Whh[(size_t)(kt * 8 + t4) * GDIM + gcol]));
            bf[kt][nt][1] = __float_as_uint(f2tf(Whh[(size_t)(kt * 8 + t4 + 4) * GDIM + gcol]));
        }

    // pointwise ownership: (row prow, h-cols pc, pc+1) of this CTA's 16x32 block
    const int prow = tid >> 4;          // 0..15
    const int pc = (tid & 15) * 2;      // 0..30
    const size_t xbase = (size_t)(cid * 16 + prow) * GDIM + r * 32 + pc;
    float* orow = out + (size_t)(cid * 16 + prow) * 256 + r * 32 + pc;
    const uint32_t as0 = sptr(&As[0][0]);
    const uint32_t doff = (uint32_t)(prow * HSTR + (int)r * 32 + pc) * 4;
    const uint32_t abase = sptr(&As[0][(lane & 15) * HSTR]) + (lane >> 4) * 16;
    float c0 = 0.f, c1 = 0.f;

    for (int t = 0; t < TSTEPS; t++) {
        float acc[2][4] = {};
        if (t) {
            uint32_t ab = abase + (uint32_t)(t & 1) * (16 * HSTR * 4);
            #pragma unroll
            for (int kt = 0; kt < 32; kt++) {
                uint32_t a[4];
                ldsm4(a, ab + kt * 32);
                mma8(acc[0], a, bf[kt][0][0], bf[kt][0][1]);
                mma8(acc[1], a, bf[kt][1][0], bf[kt][1][1]);
            }
        }
        // scatter partial gates to SMEM
        #pragma unroll
        for (int nt = 0; nt < 2; nt++) {
            int lc = w * 16 + nt * 8 + 2 * t4;
            *(float2*)&gs[g * GSTR + lc] = make_float2(acc[nt][0], acc[nt][1]);
            *(float2*)&gs[(g + 8) * GSTR + lc] = make_float2(acc[nt][2], acc[nt][3]);
        }
        __syncthreads();
        // pointwise LSTM update
        {
            const float* xr = g_xpb + (size_t)t * (256 * GDIM) + xbase;
            float2 xi = *(const float2*)(xr);
            float2 xf = *(const float2*)(xr + 256);
            float2 xg = *(const float2*)(xr + 512);
            float2 xo = *(const float2*)(xr + 768);
            float2 gi = *(float2*)&gs[prow * GSTR + pc];
            float2 gf = *(float2*)&gs[prow * GSTR + 32 + pc];
            float2 gg = *(float2*)&gs[prow * GSTR + 64 + pc];
            float2 go = *(float2*)&gs[prow * GSTR + 96 + pc];
            float i0 = sigf(gi.x + xi.x), i1 = sigf(gi.y + xi.y);
            float f0 = sigf(gf.x + xf.x), f1 = sigf(gf.y + xf.y);
            float G0 = tanhf(gg.x + xg.x), G1 = tanhf(gg.y + xg.y);
            float o0 = sigf(go.x + xo.x), o1 = sigf(go.y + xo.y);
            c0 = f0 * c0 + i0 * G0;
            c1 = f1 * c1 + i1 * G1;
            float h0 = o0 * tanhf(c0), h1 = o1 * tanhf(c1);
            *(float2*)(orow + (size_t)t * 65536) = make_float2(h0, h1);
            if (tail && t == TSTEPS - 1) {
                size_t off = (size_t)(cid * 16 + prow) * 256 + r * 32 + pc;
                *(float2*)(out + HSEQ + off) = make_float2(h0, h1);
                *(float2*)(out + HSEQ + 65536 + off) = make_float2(c0, c1);
            }
            // push tf32 h to all 8 cluster CTAs' next-step buffer
            ull hp = pack2(f2tf(h0), f2tf(h1));
            uint32_t dl = as0 + (uint32_t)(((t & 1) ^ 1) * (16 * HSTR * 4)) + doff;
            #pragma unroll
            for (uint32_t dr = 0; dr < 8; dr++)
                st_cluster64(mapa_rank(dl, dr), hp);
        }
        asm volatile("barrier.cluster.arrive.aligned;" ::: "memory");
        asm volatile("barrier.cluster.wait.aligned;" ::: "memory");
    }
}

extern "C" void kernel_launch(void* const* d_in, const int* in_sizes, int n_in,
                              void* d_out, int out_size) {
    const float* x    = (const float*)d_in[0];
    const float* wih  = (const float*)d_in[1];
    const float* whh  = (const float*)d_in[2];
    const float* bias = (const float*)d_in[3];
    float* out = (float*)d_out;
    (void)in_sizes; (void)n_in;
    proj_kernel<<<dim3(8, 8192), 256>>>(x, wih, bias);
    int tail = ((size_t)out_size >= HSEQ + 2 * 65536) ? 1 : 0;
    lstm_kernel<<<128, 256>>>(whh, out, tail);
}

// round 5
// speedup vs baseline: 1.5748x; 1.2640x over previous
#include <cuda_runtime.h>
#include <cuda_bf16.h>
#include <cstdint>
#include <cstddef>

typedef unsigned long long ull;

#define TSTEPS 1024
#define GDIM   1024
#define HSEQ   ((size_t)TSTEPS * 256 * 256)

__device__ float g_xpb[(size_t)TSTEPS * 256 * GDIM];   // x@W_ih + bias

__device__ __forceinline__ float f2tf(float x) {
    uint32_t r; asm("cvt.rna.tf32.f32 %0, %1;" : "=r"(r) : "f"(x));
    return __uint_as_float(r);
}
__device__ __forceinline__ uint32_t sptr(const void* p) {
    return (uint32_t)__cvta_generic_to_shared(p);
}
__device__ __forceinline__ void ldsm4(uint32_t a[4], uint32_t addr) {
    asm volatile("ldmatrix.sync.aligned.m8n8.x4.shared.b16 {%0,%1,%2,%3}, [%4];"
        : "=r"(a[0]), "=r"(a[1]), "=r"(a[2]), "=r"(a[3]) : "r"(addr));
}
__device__ __forceinline__ void mma8(float c[4], const uint32_t a[4], uint32_t b0, uint32_t b1) {
    asm volatile("mma.sync.aligned.m16n8k8.row.col.f32.tf32.tf32.f32 "
        "{%0,%1,%2,%3}, {%4,%5,%6,%7}, {%8,%9}, {%0,%1,%2,%3};"
        : "+f"(c[0]), "+f"(c[1]), "+f"(c[2]), "+f"(c[3])
        : "r"(a[0]), "r"(a[1]), "r"(a[2]), "r"(a[3]), "r"(b0), "r"(b1));
}
__device__ __forceinline__ float sigf(float x) { return 1.f / (1.f + __expf(-x)); }
__device__ __forceinline__ ull pack2(float x, float y) {
    ull r; asm("mov.b64 %0, {%1, %2};" : "=l"(r) : "f"(x), "f"(y)); return r;
}
__device__ __forceinline__ uint32_t mapa_rank(uint32_t addr, uint32_t rank) {
    uint32_t r;
    asm("mapa.shared::cluster.u32 %0, %1, %2;" : "=r"(r) : "r"(addr), "r"(rank));
    return r;
}
__device__ __forceinline__ void st_cluster64(uint32_t addr, ull v) {
    asm volatile("st.shared::cluster.u64 [%0], %1;" :: "r"(addr), "l"(v) : "memory");
}

// ============================================================================
// Projection: g_xpb = X(262144x256) @ W_ih(256x1024) + bias  (unchanged, works)
// ============================================================================
#define ASTR 68
#define BSTR 136

__global__ void __launch_bounds__(256) proj_kernel(const float* __restrict__ X,
                                                   const float* __restrict__ W,
                                                   const float* __restrict__ bias) {
    __shared__ float As[32 * ASTR];
    __shared__ float Bs[64 * BSTR];
    const int tid = threadIdx.x;
    const int nb = blockIdx.x * 128, mb = blockIdx.y * 32;
    const int w = tid >> 5, lane = tid & 31;
    const int g = lane >> 2, t4 = lane & 3;
    const int mw = w & 1, nw = w >> 1;

    float acc[4][4] = {};
    const uint32_t abase = sptr(As + (mw * 16 + (lane & 15)) * ASTR + (lane >> 4) * 4);

    for (int kc = 0; kc < 4; kc++) {
        if (kc) __syncthreads();
        #pragma unroll
        for (int i = 0; i < 2; i++) {
            int idx = tid + 256 * i, r = idx >> 4, c4 = idx & 15;
            float4 v = *(const float4*)(X + (size_t)(mb + r) * 256 + kc * 64 + c4 * 4);
            v.x = f2tf(v.x); v.y = f2tf(v.y); v.z = f2tf(v.z); v.w = f2tf(v.w);
            *(float4*)(As + r * ASTR + c4 * 4) = v;
        }
        #pragma unroll
        for (int i = 0; i < 8; i++) {
            int idx = tid + 256 * i, r = idx >> 5, c4 = idx & 31;
            float4 v = *(const float4*)(W + (size_t)(kc * 64 + r) * GDIM + nb + c4 * 4);
            v.x = f2tf(v.x); v.y = f2tf(v.y); v.z = f2tf(v.z); v.w = f2tf(v.w);
            *(float4*)(Bs + r * BSTR + c4 * 4) = v;
        }
        __syncthreads();
        #pragma unroll
        for (int kt = 0; kt < 8; kt++) {
            uint32_t a[4];
            ldsm4(a, abase + kt * 32);
            #pragma unroll
            for (int nt = 0; nt < 4; nt++) {
                int col = nw * 32 + nt * 8 + g;
                uint32_t b0 = __float_as_uint(Bs[(kt * 8 + t4) * BSTR + col]);
                uint32_t b1 = __float_as_uint(Bs[(kt * 8 + t4 + 4) * BSTR + col]);
                mma8(acc[nt], a, b0, b1);
            }
        }
    }
    size_t rbase = (size_t)(mb + mw * 16 + g) * GDIM;
    #pragma unroll
    for (int nt = 0; nt < 4; nt++) {
        int col = nb + nw * 32 + nt * 8 + 2 * t4;
        float b0 = __ldg(bias + col), b1 = __ldg(bias + col + 1);
        *(float2*)(g_xpb + rbase + col) = make_float2(acc[nt][0] + b0, acc[nt][1] + b1);
        *(float2*)(g_xpb + rbase + 8 * GDIM + col) = make_float2(acc[nt][2] + b0, acc[nt][3] + b1);
    }
}

// ============================================================================
// Recurrence: 8 clusters x 8 CTAs; each CTA runs TWO independent 16-row groups
// (rows 32c..32c+16 and +16..+32), interleaved to hide latency. One split
// cluster barrier per step; xp prefetched before the wait.
// ============================================================================
#define HSTR 260
#define GSTR 132
#define ASZ  (16 * HSTR)                       // floats per h buffer
#define LSMEM_FLOATS (4 * ASZ + 2 * 16 * GSTR) // 4 h-buffers + 2 gate buffers
#define LSMEM_BYTES  (LSMEM_FLOATS * 4)

__global__ void __launch_bounds__(256, 1) __cluster_dims__(8, 1, 1)
lstm_kernel(const float* __restrict__ Whh, float* __restrict__ out, int tail) {
    extern __shared__ float smem[];
    // layout: [gi=0 buf0][gi=0 buf1][gi=1 buf0][gi=1 buf1][gs0][gs1]
    const int tid = threadIdx.x;
    const int w = tid >> 5, lane = tid & 31;
    const int g = lane >> 2, t4 = lane & 3;
    const int cid = blockIdx.x >> 3;
    uint32_t r; asm("mov.u32 %0, %%cluster_ctarank;" : "=r"(r));

    // W_hh slice as persistent mma B-fragments (shared by both groups)
    uint32_t bf[32][2][2];
    #pragma unroll
    for (int kt = 0; kt < 32; kt++)
        #pragma unroll
        for (int nt = 0; nt < 2; nt++) {
            int l = w * 16 + nt * 8 + g;
            int gcol = (l >> 5) * 256 + (int)r * 32 + (l & 31);
            bf[kt][nt][0] = __float_as_uint(f2tf(Whh[(size_t)(kt * 8 + t4) * GDIM + gcol]));
            bf[kt][nt][1] = __float_as_uint(f2tf(Whh[(size_t)(kt * 8 + t4 + 4) * GDIM + gcol]));
        }

    const int prow = tid >> 4;         // 0..15
    const int pc = (tid & 15) * 2;     // 0..30
    const uint32_t smem0 = sptr(smem);
    const uint32_t aoff = (uint32_t)((lane & 15) * HSTR * 4 + (lane >> 4) * 16);
    const uint32_t doffb = (uint32_t)((prow * HSTR + (int)r * 32 + pc) * 4);
    float cst[2][2] = {};

    for (int t = 0; t < TSTEPS; t++) {
        // 1. prefetch xp for this step (overlaps barrier wait + mma)
        float2 xp[2][4];
        #pragma unroll
        for (int gi = 0; gi < 2; gi++) {
            const float* xr = g_xpb + (size_t)t * (256 * GDIM)
                            + (size_t)(cid * 32 + gi * 16 + prow) * GDIM + r * 32 + pc;
            xp[gi][0] = __ldcg((const float2*)xr);
            xp[gi][1] = __ldcg((const float2*)(xr + 256));
            xp[gi][2] = __ldcg((const float2*)(xr + 512));
            xp[gi][3] = __ldcg((const float2*)(xr + 768));
        }
        // 2. wait for previous step's cluster arrives
        if (t) asm volatile("barrier.cluster.wait.aligned;" ::: "memory");

        // 3. mma, 2 groups x 2 split accumulator chains
        float acc[2][2][4] = {};
        float acc2[2][2][4] = {};
        if (t) {
            #pragma unroll
            for (int gi = 0; gi < 2; gi++) {
                uint32_t ab = smem0 + (uint32_t)((gi * 2 + (t & 1)) * ASZ * 4) + aoff;
                #pragma unroll
                for (int kt = 0; kt < 16; kt++) {
                    uint32_t a[4];
                    ldsm4(a, ab + kt * 32);
                    mma8(acc[gi][0], a, bf[kt][0][0], bf[kt][0][1]);
                    mma8(acc[gi][1], a, bf[kt][1][0], bf[kt][1][1]);
                }
                #pragma unroll
                for (int kt = 16; kt < 32; kt++) {
                    uint32_t a[4];
                    ldsm4(a, ab + kt * 32);
                    mma8(acc2[gi][0], a, bf[kt][0][0], bf[kt][0][1]);
                    mma8(acc2[gi][1], a, bf[kt][1][0], bf[kt][1][1]);
                }
            }
        }
        // 4. scatter gates to SMEM
        #pragma unroll
        for (int gi = 0; gi < 2; gi++) {
            float* gsp = smem + 4 * ASZ + gi * 16 * GSTR;
            #pragma unroll
            for (int nt = 0; nt < 2; nt++) {
                int lc = w * 16 + nt * 8 + 2 * t4;
                *(float2*)&gsp[g * GSTR + lc] =
                    make_float2(acc[gi][nt][0] + acc2[gi][nt][0], acc[gi][nt][1] + acc2[gi][nt][1]);
                *(float2*)&gsp[(g + 8) * GSTR + lc] =
                    make_float2(acc[gi][nt][2] + acc2[gi][nt][2], acc[gi][nt][3] + acc2[gi][nt][3]);
            }
        }
        __syncthreads();
        // 5. pointwise + DSMEM push + out
        #pragma unroll
        for (int gi = 0; gi < 2; gi++) {
            float* gsp = smem + 4 * ASZ + gi * 16 * GSTR;
            float2 vi = *(float2*)&gsp[prow * GSTR + pc];
            float2 vf = *(float2*)&gsp[prow * GSTR + 32 + pc];
            float2 vg = *(float2*)&gsp[prow * GSTR + 64 + pc];
            float2 vo = *(float2*)&gsp[prow * GSTR + 96 + pc];
            float i0 = sigf(vi.x + xp[gi][0].x), i1 = sigf(vi.y + xp[gi][0].y);
            float f0 = sigf(vf.x + xp[gi][1].x), f1 = sigf(vf.y + xp[gi][1].y);
            float G0 = tanhf(vg.x + xp[gi][2].x), G1 = tanhf(vg.y + xp[gi][2].y);
            float o0 = sigf(vo.x + xp[gi][3].x), o1 = sigf(vo.y + xp[gi][3].y);
            cst[gi][0] = f0 * cst[gi][0] + i0 * G0;
            cst[gi][1] = f1 * cst[gi][1] + i1 * G1;
            float h0 = o0 * tanhf(cst[gi][0]), h1 = o1 * tanhf(cst[gi][1]);
            // push tf32 h to all 8 cluster CTAs' next-step buffer (do first)
            ull hp = pack2(f2tf(h0), f2tf(h1));
            uint32_t dl = smem0 + (uint32_t)((gi * 2 + ((t & 1) ^ 1)) * ASZ * 4) + doffb;
            #pragma unroll
            for (uint32_t dr = 0; dr < 8; dr++)
                st_cluster64(mapa_rank(dl, dr), hp);
            // stream h out
            size_t off = (size_t)(cid * 32 + gi * 16 + prow) * 256 + r * 32 + pc;
            *(float2*)(out + (size_t)t * 65536 + off) = make_float2(h0, h1);
            if (tail && t == TSTEPS - 1) {
                *(float2*)(out + HSEQ + off) = make_float2(h0, h1);
                *(float2*)(out + HSEQ + 65536 + off) = make_float2(cst[gi][0], cst[gi][1]);
            }
        }
        // 6. release this step
        asm volatile("barrier.cluster.arrive.aligned;" ::: "memory");
    }
}

extern "C" void kernel_launch(void* const* d_in, const int* in_sizes, int n_in,
                              void* d_out, int out_size) {
    const float* x    = (const float*)d_in[0];
    const float* wih  = (const float*)d_in[1];
    const float* whh  = (const float*)d_in[2];
    const float* bias = (const float*)d_in[3];
    float* out = (float*)d_out;
    (void)in_sizes; (void)n_in;
    cudaFuncSetAttribute(lstm_kernel, cudaFuncAttributeMaxDynamicSharedMemorySize, LSMEM_BYTES);
    proj_kernel<<<dim3(8, 8192), 256>>>(x, wih, bias);
    int tail = ((size_t)out_size >= HSEQ + 2 * 65536) ? 1 : 0;
    lstm_kernel<<<64, 256, LSMEM_BYTES>>>(whh, out, tail);
}

// round 6
// speedup vs baseline: 1.8261x; 1.1596x over previous
#include <cuda_runtime.h>
#include <cuda_bf16.h>
#include <cstdint>
#include <cstddef>

typedef unsigned long long ull;

#define TSTEPS 1024
#define GDIM   1024
#define HSEQ   ((size_t)TSTEPS * 256 * 256)

__device__ float g_xpb[(size_t)TSTEPS * 256 * GDIM];   // x@W_ih + bias

__device__ __forceinline__ float f2tf(float x) {
    uint32_t r; asm("cvt.rna.tf32.f32 %0, %1;" : "=r"(r) : "f"(x));
    return __uint_as_float(r);
}
__device__ __forceinline__ uint32_t sptr(const void* p) {
    return (uint32_t)__cvta_generic_to_shared(p);
}
__device__ __forceinline__ void ldsm4(uint32_t a[4], uint32_t addr) {
    asm volatile("ldmatrix.sync.aligned.m8n8.x4.shared.b16 {%0,%1,%2,%3}, [%4];"
        : "=r"(a[0]), "=r"(a[1]), "=r"(a[2]), "=r"(a[3]) : "r"(addr));
}
__device__ __forceinline__ void mma8(float c[4], const uint32_t a[4], uint32_t b0, uint32_t b1) {
    asm volatile("mma.sync.aligned.m16n8k8.row.col.f32.tf32.tf32.f32 "
        "{%0,%1,%2,%3}, {%4,%5,%6,%7}, {%8,%9}, {%0,%1,%2,%3};"
        : "+f"(c[0]), "+f"(c[1]), "+f"(c[2]), "+f"(c[3])
        : "r"(a[0]), "r"(a[1]), "r"(a[2]), "r"(a[3]), "r"(b0), "r"(b1));
}
__device__ __forceinline__ float sigf(float x) { return 1.f / (1.f + __expf(-x)); }
__device__ __forceinline__ uint32_t mapa_rank(uint32_t addr, uint32_t rank) {
    uint32_t r;
    asm("mapa.shared::cluster.u32 %0, %1, %2;" : "=r"(r) : "r"(addr), "r"(rank));
    return r;
}
__device__ __forceinline__ void mbar_init(uint32_t a, uint32_t cnt) {
    asm volatile("mbarrier.init.shared.b64 [%0], %1;" :: "r"(a), "r"(cnt) : "memory");
}
__device__ __forceinline__ void mbar_expect(uint32_t a, uint32_t bytes) {
    asm volatile("mbarrier.arrive.expect_tx.shared.b64 _, [%0], %1;" :: "r"(a), "r"(bytes) : "memory");
}
__device__ __forceinline__ void mbar_wait(uint32_t a, uint32_t parity) {
    asm volatile(
        "{\n\t.reg .pred P;\n\t"
        "WL_%=:\n\t"
        "mbarrier.try_wait.parity.acquire.cta.shared::cta.b64 P, [%0], %1, 0x989680;\n\t"
        "@P bra.uni WD_%=;\n\t"
        "bra.uni WL_%=;\n\t"
        "WD_%=:\n\t}"
        :: "r"(a), "r"(parity) : "memory");
}
__device__ __forceinline__ void bulk_s2s(uint32_t dst, uint32_t src, uint32_t bytes, uint32_t mbar) {
    asm volatile("cp.async.bulk.shared::cluster.shared::cta.mbarrier::complete_tx::bytes "
                 "[%0], [%1], %2, [%3];"
        :: "r"(dst), "r"(src), "r"(bytes), "r"(mbar) : "memory");
}

// ============================================================================
// Projection: g_xpb = X(262144x256) @ W_ih(256x1024) + bias  (unchanged)
// ============================================================================
#define ASTR 68
#define BSTR 136

__global__ void __launch_bounds__(256) proj_kernel(const float* __restrict__ X,
                                                   const float* __restrict__ W,
                                                   const float* __restrict__ bias) {
    __shared__ float As[32 * ASTR];
    __shared__ float Bs[64 * BSTR];
    const int tid = threadIdx.x;
    const int nb = blockIdx.x * 128, mb = blockIdx.y * 32;
    const int w = tid >> 5, lane = tid & 31;
    const int g = lane >> 2, t4 = lane & 3;
    const int mw = w & 1, nw = w >> 1;

    float acc[4][4] = {};
    const uint32_t abase = sptr(As + (mw * 16 + (lane & 15)) * ASTR + (lane >> 4) * 4);

    for (int kc = 0; kc < 4; kc++) {
        if (kc) __syncthreads();
        #pragma unroll
        for (int i = 0; i < 2; i++) {
            int idx = tid + 256 * i, r = idx >> 4, c4 = idx & 15;
            float4 v = *(const float4*)(X + (size_t)(mb + r) * 256 + kc * 64 + c4 * 4);
            v.x = f2tf(v.x); v.y = f2tf(v.y); v.z = f2tf(v.z); v.w = f2tf(v.w);
            *(float4*)(As + r * ASTR + c4 * 4) = v;
        }
        #pragma unroll
        for (int i = 0; i < 8; i++) {
            int idx = tid + 256 * i, r = idx >> 5, c4 = idx & 31;
            float4 v = *(const float4*)(W + (size_t)(kc * 64 + r) * GDIM + nb + c4 * 4);
            v.x = f2tf(v.x); v.y = f2tf(v.y); v.z = f2tf(v.z); v.w = f2tf(v.w);
            *(float4*)(Bs + r * BSTR + c4 * 4) = v;
        }
        __syncthreads();
        #pragma unroll
        for (int kt = 0; kt < 8; kt++) {
            uint32_t a[4];
            ldsm4(a, abase + kt * 32);
            #pragma unroll
            for (int nt = 0; nt < 4; nt++) {
                int col = nw * 32 + nt * 8 + g;
                uint32_t b0 = __float_as_uint(Bs[(kt * 8 + t4) * BSTR + col]);
                uint32_t b1 = __float_as_uint(Bs[(kt * 8 + t4 + 4) * BSTR + col]);
                mma8(acc[nt], a, b0, b1);
            }
        }
    }
    size_t rbase = (size_t)(mb + mw * 16 + g) * GDIM;
    #pragma unroll
    for (int nt = 0; nt < 4; nt++) {
        int col = nb + nw * 32 + nt * 8 + 2 * t4;
        float b0 = __ldg(bias + col), b1 = __ldg(bias + col + 1);
        *(float2*)(g_xpb + rbase + col) = make_float2(acc[nt][0] + b0, acc[nt][1] + b1);
        *(float2*)(g_xpb + rbase + 8 * GDIM + col) = make_float2(acc[nt][2] + b0, acc[nt][3] + b1);
    }
}

// ============================================================================
// Recurrence: 8 clusters x 8 CTAs, 2 groups of 16 rows per CTA.
// h exchange = staged 2KB block -> 8x cp.async.bulk (DSMEM) with complete_tx.
// Per-(group,buffer) mbarriers; no cluster barrier in steady state.
// SMEM floats: As[gi][b] 4x4096 (blocked 8x(16x32), XOR-swizzled) |
//              gs[gi] 2x2112 | stage[gi] 2x512 | mbarriers 4x8B
// ============================================================================
#define GSTR 132
#define AS_F(gi,b) (((gi)*2+(b))*4096)
#define GS_F(gi)   (16384 + (gi)*2112)
#define ST_F(gi)   (20608 + (gi)*512)
#define MB_BYTE    86528
#define LSMEM_BYTES 86560

__global__ void __launch_bounds__(256, 1) __cluster_dims__(8, 1, 1)
lstm_kernel(const float* __restrict__ Whh, float* __restrict__ out, int tail) {
    extern __shared__ float smem[];
    const uint32_t smem0 = sptr(smem);
    const int tid = threadIdx.x;
    const int w = tid >> 5, lane = tid & 31;
    const int g = lane >> 2, t4 = lane & 3;
    const int cid = blockIdx.x >> 3;
    uint32_t r; asm("mov.u32 %0, %%cluster_ctarank;" : "=r"(r));

    // init mbarriers + pre-post phase-0 expectations (16KB per buffer fill)
    if (tid == 0) {
        #pragma unroll
        for (int i = 0; i < 4; i++) mbar_init(smem0 + MB_BYTE + i * 8, 1);
        #pragma unroll
        for (int i = 0; i < 4; i++) mbar_expect(smem0 + MB_BYTE + i * 8, 16384);
    }

    // W_hh slice as persistent mma B-fragments
    uint32_t bf[32][2][2];
    #pragma unroll
    for (int kt = 0; kt < 32; kt++)
        #pragma unroll
        for (int nt = 0; nt < 2; nt++) {
            int l = w * 16 + nt * 8 + g;
            int gcol = (l >> 5) * 256 + (int)r * 32 + (l & 31);
            bf[kt][nt][0] = __float_as_uint(f2tf(Whh[(size_t)(kt * 8 + t4) * GDIM + gcol]));
            bf[kt][nt][1] = __float_as_uint(f2tf(Whh[(size_t)(kt * 8 + t4 + 4) * GDIM + gcol]));
        }
    __syncthreads();
    asm volatile("barrier.cluster.arrive.aligned;" ::: "memory");
    asm volatile("barrier.cluster.wait.aligned;" ::: "memory");

    // ldsm lane addressing on blocked+swizzled layout
    const int laneRow = lane & 15, cb = lane >> 4, rx = laneRow & 7;
    const uint32_t rowbase = (uint32_t)laneRow * 128;

    // pointwise / staging ownership
    const int prow = tid >> 4;          // 0..15
    const int pc = (tid & 15) * 2;      // 0..30
    const int schunk = (pc >> 2) ^ (prow & 7);
    const int stoff = prow * 32 + schunk * 4 + (pc & 3);   // floats
    float cst[2][2] = {};
    int ph[2][2] = {{0, 0}, {0, 0}};

    for (int t = 0; t < TSTEPS; t++) {
        const int b = t & 1, nbuf = b ^ 1;
        // prefetch xp for both groups
        float2 xp[2][4];
        #pragma unroll
        for (int gi = 0; gi < 2; gi++) {
            const float* xr = g_xpb + (size_t)t * (256 * GDIM)
                            + (size_t)(cid * 32 + gi * 16 + prow) * GDIM + r * 32 + pc;
            xp[gi][0] = __ldcg((const float2*)xr);
            xp[gi][1] = __ldcg((const float2*)(xr + 256));
            xp[gi][2] = __ldcg((const float2*)(xr + 512));
            xp[gi][3] = __ldcg((const float2*)(xr + 768));
        }
        #pragma unroll
        for (int gi = 0; gi < 2; gi++) {
            float acc[2][4] = {}, acc2[2][4] = {};
            if (t) {
                uint32_t mb = smem0 + MB_BYTE + (gi * 2 + b) * 8;
                mbar_wait(mb, (uint32_t)ph[gi][b]);
                ph[gi][b] ^= 1;
                if (tid == 0) mbar_expect(mb, 16384);
                uint32_t ab = smem0 + AS_F(gi, b) * 4 + rowbase;
                #pragma unroll
                for (int kt = 0; kt < 16; kt++) {
                    uint32_t a[4];
                    uint32_t c = (uint32_t)(((((kt & 3) << 1) | cb) ^ rx) << 4);
                    ldsm4(a, ab + ((kt >> 2) << 11) + c);
                    mma8(acc[0], a, bf[kt][0][0], bf[kt][0][1]);
                    mma8(acc[1], a, bf[kt][1][0], bf[kt][1][1]);
                }
                #pragma unroll
                for (int kt = 16; kt < 32; kt++) {
                    uint32_t a[4];
                    uint32_t c = (uint32_t)(((((kt & 3) << 1) | cb) ^ rx) << 4);
                    ldsm4(a, ab + ((kt >> 2) << 11) + c);
                    mma8(acc2[0], a, bf[kt][0][0], bf[kt][0][1]);
                    mma8(acc2[1], a, bf[kt][1][0], bf[kt][1][1]);
                }
            }
            // scatter gates
            float* gsp = smem + GS_F(gi);
            #pragma unroll
            for (int nt = 0; nt < 2; nt++) {
                int lc = w * 16 + nt * 8 + 2 * t4;
                *(float2*)&gsp[g * GSTR + lc] =
                    make_float2(acc[nt][0] + acc2[nt][0], acc[nt][1] + acc2[nt][1]);
                *(float2*)&gsp[(g + 8) * GSTR + lc] =
                    make_float2(acc[nt][2] + acc2[nt][2], acc[nt][3] + acc2[nt][3]);
            }
            __syncthreads();
            // pointwise
            float2 vi = *(float2*)&gsp[prow * GSTR + pc];
            float2 vf = *(float2*)&gsp[prow * GSTR + 32 + pc];
            float2 vg = *(float2*)&gsp[prow * GSTR + 64 + pc];
            float2 vo = *(float2*)&gsp[prow * GSTR + 96 + pc];
            float i0 = sigf(vi.x + xp[gi][0].x), i1 = sigf(vi.y + xp[gi][0].y);
            float f0 = sigf(vf.x + xp[gi][1].x), f1 = sigf(vf.y + xp[gi][1].y);
            float G0 = tanhf(vg.x + xp[gi][2].x), G1 = tanhf(vg.y + xp[gi][2].y);
            float o0 = sigf(vo.x + xp[gi][3].x), o1 = sigf(vo.y + xp[gi][3].y);
            cst[gi][0] = f0 * cst[gi][0] + i0 * G0;
            cst[gi][1] = f1 * cst[gi][1] + i1 * G1;
            float h0 = o0 * tanhf(cst[gi][0]), h1 = o1 * tanhf(cst[gi][1]);
            // stage swizzled tf32 block for the bulk push
            *(float2*)(smem + ST_F(gi) + stoff) = make_float2(f2tf(h0), f2tf(h1));
            // stream h out
            size_t off = (size_t)(cid * 32 + gi * 16 + prow) * 256 + r * 32 + pc;
            *(float2*)(out + (size_t)t * 65536 + off) = make_float2(h0, h1);
            if (tail && t == TSTEPS - 1) {
                *(float2*)(out + HSEQ + off) = make_float2(h0, h1);
                *(float2*)(out + HSEQ + 65536 + off) = make_float2(cst[gi][0], cst[gi][1]);
            }
            __syncthreads();
            // async push: 8 x 2KB bulk copies with complete_tx at destinations
            if (tid == 0 && t < TSTEPS - 1) {
                asm volatile("fence.proxy.async.shared::cta;" ::: "memory");
                uint32_t src = smem0 + ST_F(gi) * 4;
                uint32_t dstl = smem0 + AS_F(gi, nbuf) * 4 + r * 2048;
                uint32_t mbl = smem0 + MB_BYTE + (gi * 2 + nbuf) * 8;
                #pragma unroll
                for (uint32_t dr = 0; dr < 8; dr++)
                    bulk_s2s(mapa_rank(dstl, dr), src, 2048u, mapa_rank(mbl, dr));
            }
        }
    }
    // teardown: ensure our bulk-copy source reads are done, then cluster sync
    if (tid == 0) {
        asm volatile("cp.async.bulk.commit_group;" ::: "memory");
        asm volatile("cp.async.bulk.wait_group.read 0;" ::: "memory");
    }
    __syncthreads();
    asm volatile("barrier.cluster.arrive.aligned;" ::: "memory");
    asm volatile("barrier.cluster.wait.aligned;" ::: "memory");
}

extern "C" void kernel_launch(void* const* d_in, const int* in_sizes, int n_in,
                              void* d_out, int out_size) {
    const float* x    = (const float*)d_in[0];
    const float* wih  = (const float*)d_in[1];
    const float* whh  = (const float*)d_in[2];
    const float* bias = (const float*)d_in[3];
    float* out = (float*)d_out;
    (void)in_sizes; (void)n_in;
    cudaFuncSetAttribute(lstm_kernel, cudaFuncAttributeMaxDynamicSharedMemorySize, LSMEM_BYTES);
    proj_kernel<<<dim3(8, 8192), 256>>>(x, wih, bias);
    int tail = ((size_t)out_size >= HSEQ + 2 * 65536) ? 1 : 0;
    lstm_kernel<<<64, 256, LSMEM_BYTES>>>(whh, out, tail);
}

// round 7
// speedup vs baseline: 2.0525x; 1.1240x over previous
#include <cuda_runtime.h>
#include <cuda_bf16.h>
#include <cstdint>
#include <cstddef>

typedef unsigned long long ull;

#define TSTEPS 1024
#define GDIM   1024
#define HSEQ   ((size_t)TSTEPS * 256 * 256)

__device__ float g_xpb[(size_t)TSTEPS * 256 * GDIM];   // x@W_ih + bias

__device__ __forceinline__ float f2tf(float x) {
    uint32_t r; asm("cvt.rna.tf32.f32 %0, %1;" : "=r"(r) : "f"(x));
    return __uint_as_float(r);
}
__device__ __forceinline__ uint32_t sptr(const void* p) {
    return (uint32_t)__cvta_generic_to_shared(p);
}
__device__ __forceinline__ void ldsm4(uint32_t a[4], uint32_t addr) {
    asm volatile("ldmatrix.sync.aligned.m8n8.x4.shared.b16 {%0,%1,%2,%3}, [%4];"
        : "=r"(a[0]), "=r"(a[1]), "=r"(a[2]), "=r"(a[3]) : "r"(addr));
}
__device__ __forceinline__ void mma8(float c[4], const uint32_t a[4], uint32_t b0, uint32_t b1) {
    asm volatile("mma.sync.aligned.m16n8k8.row.col.f32.tf32.tf32.f32 "
        "{%0,%1,%2,%3}, {%4,%5,%6,%7}, {%8,%9}, {%0,%1,%2,%3};"
        : "+f"(c[0]), "+f"(c[1]), "+f"(c[2]), "+f"(c[3])
        : "r"(a[0]), "r"(a[1]), "r"(a[2]), "r"(a[3]), "r"(b0), "r"(b1));
}
__device__ __forceinline__ float sigf(float x) { return 1.f / (1.f + __expf(-x)); }
__device__ __forceinline__ ull pack2(float x, float y) {
    ull r; asm("mov.b64 %0, {%1, %2};" : "=l"(r) : "f"(x), "f"(y)); return r;
}
__device__ __forceinline__ uint32_t mapa_rank(uint32_t addr, uint32_t rank) {
    uint32_t r;
    asm("mapa.shared::cluster.u32 %0, %1, %2;" : "=r"(r) : "r"(addr), "r"(rank));
    return r;
}
__device__ __forceinline__ void mbar_init(uint32_t a, uint32_t cnt) {
    asm volatile("mbarrier.init.shared.b64 [%0], %1;" :: "r"(a), "r"(cnt) : "memory");
}
__device__ __forceinline__ void mbar_expect(uint32_t a, uint32_t bytes) {
    asm volatile("mbarrier.arrive.expect_tx.shared.b64 _, [%0], %1;" :: "r"(a), "r"(bytes) : "memory");
}
__device__ __forceinline__ void mbar_wait(uint32_t a, uint32_t parity) {
    asm volatile(
        "{\n\t.reg .pred P;\n\t"
        "WL_%=:\n\t"
        "mbarrier.try_wait.parity.acquire.cta.shared::cta.b64 P, [%0], %1, 0x989680;\n\t"
        "@P bra.uni WD_%=;\n\t"
        "bra.uni WL_%=;\n\t"
        "WD_%=:\n\t}"
        :: "r"(a), "r"(parity) : "memory");
}
__device__ __forceinline__ void st_async64(uint32_t dst, ull v, uint32_t mbar) {
    asm volatile("st.async.shared::cluster.mbarrier::complete_tx::bytes.b64 [%0], %1, [%2];"
        :: "r"(dst), "l"(v), "r"(mbar) : "memory");
}

// ============================================================================
// Projection: g_xpb = X(262144x256) @ W_ih(256x1024) + bias
// CTA tile 128M x 128N, 8 warps (2m x 4n), warp tile 64x32, K chunks of 64.
// ============================================================================
#define PASTR 68
#define PBSTR 136
#define PROJ_SMEM ((128 * PASTR + 64 * PBSTR) * 4)

__global__ void __launch_bounds__(256) proj_kernel(const float* __restrict__ X,
                                                   const float* __restrict__ W,
                                                   const float* __restrict__ bias) {
    extern __shared__ float sm[];
    float* As = sm;                 // 128 x 68
    float* Bs = sm + 128 * PASTR;   // 64 x 136
    const int tid = threadIdx.x;
    const int nb = blockIdx.x * 128, mb = blockIdx.y * 128;
    const int w = tid >> 5, lane = tid & 31;
    const int g = lane >> 2, t4 = lane & 3;
    const int mw = w & 1, nw = w >> 1;    // m-base mw*64, n-base nw*32

    float acc[4][4][4] = {};
    const uint32_t abase = sptr(As + (mw * 64 + (lane & 15)) * PASTR + (lane >> 4) * 4);

    for (int kc = 0; kc < 4; kc++) {
        if (kc) __syncthreads();
        // stage A 128x64 (tf32-rounded)
        #pragma unroll
        for (int i = 0; i < 8; i++) {
            int idx = tid + 256 * i, r = idx >> 4, c4 = idx & 15;
            float4 v = *(const float4*)(X + (size_t)(mb + r) * 256 + kc * 64 + c4 * 4);
            v.x = f2tf(v.x); v.y = f2tf(v.y); v.z = f2tf(v.z); v.w = f2tf(v.w);
            *(float4*)(As + r * PASTR + c4 * 4) = v;
        }
        // stage B 64x128 (tf32-rounded)
        #pragma unroll
        for (int i = 0; i < 8; i++) {
            int idx = tid + 256 * i, r = idx >> 5, c4 = idx & 31;
            float4 v = *(const float4*)(W + (size_t)(kc * 64 + r) * GDIM + nb + c4 * 4);
            v.x = f2tf(v.x); v.y = f2tf(v.y); v.z = f2tf(v.z); v.w = f2tf(v.w);
            *(float4*)(Bs + r * PBSTR + c4 * 4) = v;
        }
        __syncthreads();
        #pragma unroll
        for (int kt = 0; kt < 8; kt++) {
            uint32_t af[4][4];
            #pragma unroll
            for (int mt = 0; mt < 4; mt++)
                ldsm4(af[mt], abase + (uint32_t)(mt * 16 * PASTR * 4) + kt * 32);
            #pragma unroll
            for (int nt = 0; nt < 4; nt++) {
                int col = nw * 32 + nt * 8 + g;
                uint32_t b0 = __float_as_uint(Bs[(kt * 8 + t4) * PBSTR + col]);
                uint32_t b1 = __float_as_uint(Bs[(kt * 8 + t4 + 4) * PBSTR + col]);
                #pragma unroll
                for (int mt = 0; mt < 4; mt++) mma8(acc[mt][nt], af[mt], b0, b1);
            }
        }
    }
    #pragma unroll
    for (int mt = 0; mt < 4; mt++) {
        size_t r0 = (size_t)(mb + mw * 64 + mt * 16 + g);
        #pragma unroll
        for (int nt = 0; nt < 4; nt++) {
            int col = nb + nw * 32 + nt * 8 + 2 * t4;
            float b0 = __ldg(bias + col), b1 = __ldg(bias + col + 1);
            *(float2*)(g_xpb + r0 * GDIM + col) =
                make_float2(acc[mt][nt][0] + b0, acc[mt][nt][1] + b1);
            *(float2*)(g_xpb + (r0 + 8) * GDIM + col) =
                make_float2(acc[mt][nt][2] + b0, acc[mt][nt][3] + b1);
        }
    }
}

// ============================================================================
// Recurrence: 8 clusters x 8 CTAs, 2 groups of 16 rows per CTA.
// h exchange = per-thread st.async (DSMEM, complete_tx) into the swizzled
// blocked buffers. One syncthreads per group; gate buffers parity-doubled.
// ============================================================================
#define GSTR 132
#define AS_F(gi,b) (((gi)*2+(b))*4096)
#define GS_F(gi,p) (16384 + ((gi)*2+(p))*2112)
#define MB_BYTE    99328
#define LSMEM_BYTES 99360

__global__ void __launch_bounds__(256, 1) __cluster_dims__(8, 1, 1)
lstm_kernel(const float* __restrict__ Whh, float* __restrict__ out, int tail) {
    extern __shared__ float smem[];
    const uint32_t smem0 = sptr(smem);
    const int tid = threadIdx.x;
    const int w = tid >> 5, lane = tid & 31;
    const int g = lane >> 2, t4 = lane & 3;
    const int cid = blockIdx.x >> 3;
    uint32_t r; asm("mov.u32 %0, %%cluster_ctarank;" : "=r"(r));

    if (tid == 0) {
        #pragma unroll
        for (int i = 0; i < 4; i++) mbar_init(smem0 + MB_BYTE + i * 8, 1);
        #pragma unroll
        for (int i = 0; i < 4; i++) mbar_expect(smem0 + MB_BYTE + i * 8, 16384);
    }

    // W_hh slice as persistent mma B-fragments
    uint32_t bf[32][2][2];
    #pragma unroll
    for (int kt = 0; kt < 32; kt++)
        #pragma unroll
        for (int nt = 0; nt < 2; nt++) {
            int l = w * 16 + nt * 8 + g;
            int gcol = (l >> 5) * 256 + (int)r * 32 + (l & 31);
            bf[kt][nt][0] = __float_as_uint(f2tf(Whh[(size_t)(kt * 8 + t4) * GDIM + gcol]));
            bf[kt][nt][1] = __float_as_uint(f2tf(Whh[(size_t)(kt * 8 + t4 + 4) * GDIM + gcol]));
        }
    __syncthreads();
    asm volatile("barrier.cluster.arrive.aligned;" ::: "memory");
    asm volatile("barrier.cluster.wait.aligned;" ::: "memory");

    // peer SMEM bases (mapa is offset-preserving)
    uint32_t peer[8];
    #pragma unroll
    for (int dr = 0; dr < 8; dr++) peer[dr] = mapa_rank(smem0, (uint32_t)dr);

    // ldsm lane addressing on blocked+swizzled layout
    const int laneRow = lane & 15, cb = lane >> 4, rx = laneRow & 7;
    const uint32_t rowbase = (uint32_t)laneRow * 128;

    // pointwise / push ownership
    const int prow = tid >> 4;          // 0..15
    const int pc = (tid & 15) * 2;      // 0..30
    const int schunk = (pc >> 2) ^ (prow & 7);
    const int stoff = prow * 32 + schunk * 4 + (pc & 3);   // floats within 2KB block
    float cst[2][2] = {};
    int ph[2][2] = {{0, 0}, {0, 0}};

    for (int t = 0; t < TSTEPS; t++) {
        const int b = t & 1, nbuf = b ^ 1;
        // prefetch xp for both groups
        float2 xp[2][4];
        #pragma unroll
        for (int gi = 0; gi < 2; gi++) {
            const float* xr = g_xpb + (size_t)t * (256 * GDIM)
                            + (size_t)(cid * 32 + gi * 16 + prow) * GDIM + r * 32 + pc;
            xp[gi][0] = __ldcg((const float2*)xr);
            xp[gi][1] = __ldcg((const float2*)(xr + 256));
            xp[gi][2] = __ldcg((const float2*)(xr + 512));
            xp[gi][3] = __ldcg((const float2*)(xr + 768));
        }
        #pragma unroll
        for (int gi = 0; gi < 2; gi++) {
            float acc[2][4] = {}, acc2[2][4] = {};
            if (t) {
                uint32_t mb = smem0 + MB_BYTE + (gi * 2 + b) * 8;
                mbar_wait(mb, (uint32_t)ph[gi][b]);
                ph[gi][b] ^= 1;
                if (tid == 0) mbar_expect(mb, 16384);
                uint32_t ab = smem0 + AS_F(gi, b) * 4 + rowbase;
                #pragma unroll
                for (int kt = 0; kt < 16; kt++) {
                    uint32_t a[4];
                    uint32_t c = (uint32_t)(((((kt & 3) << 1) | cb) ^ rx) << 4);
                    ldsm4(a, ab + ((kt >> 2) << 11) + c);
                    mma8(acc[0], a, bf[kt][0][0], bf[kt][0][1]);
                    mma8(acc[1], a, bf[kt][1][0], bf[kt][1][1]);
                }
                #pragma unroll
                for (int kt = 16; kt < 32; kt++) {
                    uint32_t a[4];
                    uint32_t c = (uint32_t)(((((kt & 3) << 1) | cb) ^ rx) << 4);
                    ldsm4(a, ab + ((kt >> 2) << 11) + c);
                    mma8(acc2[0], a, bf[kt][0][0], bf[kt][0][1]);
                    mma8(acc2[1], a, bf[kt][1][0], bf[kt][1][1]);
                }
            }
            // scatter gates (parity-doubled buffer)
            float* gsp = smem + GS_F(gi, b);
            #pragma unroll
            for (int nt = 0; nt < 2; nt++) {
                int lc = w * 16 + nt * 8 + 2 * t4;
                *(float2*)&gsp[g * GSTR + lc] =
                    make_float2(acc[nt][0] + acc2[nt][0], acc[nt][1] + acc2[nt][1]);
                *(float2*)&gsp[(g + 8) * GSTR + lc] =
                    make_float2(acc[nt][2] + acc2[nt][2], acc[nt][3] + acc2[nt][3]);
            }
            __syncthreads();
            // pointwise
            float2 vi = *(float2*)&gsp[prow * GSTR + pc];
            float2 vf = *(float2*)&gsp[prow * GSTR + 32 + pc];
            float2 vg = *(float2*)&gsp[prow * GSTR + 64 + pc];
            float2 vo = *(float2*)&gsp[prow * GSTR + 96 + pc];
            float i0 = sigf(vi.x + xp[gi][0].x), i1 = sigf(vi.y + xp[gi][0].y);
            float f0 = sigf(vf.x + xp[gi][1].x), f1 = sigf(vf.y + xp[gi][1].y);
            float G0 = tanhf(vg.x + xp[gi][2].x), G1 = tanhf(vg.y + xp[gi][2].y);
            float o0 = sigf(vo.x + xp[gi][3].x), o1 = sigf(vo.y + xp[gi][3].y);
            cst[gi][0] = f0 * cst[gi][0] + i0 * G0;
            cst[gi][1] = f1 * cst[gi][1] + i1 * G1;
            float h0 = o0 * tanhf(cst[gi][0]), h1 = o1 * tanhf(cst[gi][1]);
            // direct async push to all 8 peers (starts immediately, no staging)
            if (t < TSTEPS - 1) {
                ull hp = pack2(f2tf(h0), f2tf(h1));
                uint32_t doff = (uint32_t)((AS_F(gi, nbuf) + (int)r * 512 + stoff) * 4);
                uint32_t moff = (uint32_t)(MB_BYTE + (gi * 2 + nbuf) * 8);
                #pragma unroll
                for (int dr = 0; dr < 8; dr++)
                    st_async64(peer[dr] + doff, hp, peer[dr] + moff);
            }
            // stream h out
            size_t off = (size_t)(cid * 32 + gi * 16 + prow) * 256 + r * 32 + pc;
            *(float2*)(out + (size_t)t * 65536 + off) = make_float2(h0, h1);
            if (tail && t == TSTEPS - 1) {
                *(float2*)(out + HSEQ + off) = make_float2(h0, h1);
                *(float2*)(out + HSEQ + 65536 + off) = make_float2(cst[gi][0], cst[gi][1]);
            }
        }
    }
    __syncthreads();
    asm volatile("barrier.cluster.arrive.aligned;" ::: "memory");
    asm volatile("barrier.cluster.wait.aligned;" ::: "memory");
}

extern "C" void kernel_launch(void* const* d_in, const int* in_sizes, int n_in,
                              void* d_out, int out_size) {
    const float* x    = (const float*)d_in[0];
    const float* wih  = (const float*)d_in[1];
    const float* whh  = (const float*)d_in[2];
    const float* bias = (const float*)d_in[3];
    float* out = (float*)d_out;
    (void)in_sizes; (void)n_in;
    cudaFuncSetAttribute(proj_kernel, cudaFuncAttributeMaxDynamicSharedMemorySize, PROJ_SMEM);
    cudaFuncSetAttribute(lstm_kernel, cudaFuncAttributeMaxDynamicSharedMemorySize, LSMEM_BYTES);
    proj_kernel<<<dim3(8, 2048), 256, PROJ_SMEM>>>(x, wih, bias);
    int tail = ((size_t)out_size >= HSEQ + 2 * 65536) ? 1 : 0;
    lstm_kernel<<<64, 256, LSMEM_BYTES>>>(whh, out, tail);
}